// round 4
// baseline (speedup 1.0000x reference)
#include <cuda_runtime.h>
#include <math.h>

#define D 32
#define H 128
#define NB 128
#define NSTEPS 8
#define DTf 0.125f
#define LOG2PI 1.837877066409345483560659472811f

// E[m*H+k] = W2[m,k] * (W1 @ W3)[k,m]   (input-independent)
__device__ float g_E[H * H];

static __device__ constexpr float Aa[6][5] = {
    {0.f, 0.f, 0.f, 0.f, 0.f},
    {0.2f, 0.f, 0.f, 0.f, 0.f},
    {3.f/40.f, 9.f/40.f, 0.f, 0.f, 0.f},
    {44.f/45.f, -56.f/15.f, 32.f/9.f, 0.f, 0.f},
    {19372.f/6561.f, -25360.f/2187.f, 64448.f/6561.f, -212.f/729.f, 0.f},
    {9017.f/3168.f, -355.f/33.f, 46732.f/5247.f, 49.f/176.f, -5103.f/18656.f}
};
static __device__ constexpr float Bb[6] = {
    35.f/384.f, 0.f, 500.f/1113.f, 125.f/192.f, -2187.f/6784.f, 11.f/84.f
};
static __device__ constexpr float Cc[6] = {0.f, 0.2f, 0.3f, 0.8f, 8.f/9.f, 1.f};

__global__ void precompute_E_kernel(const float* __restrict__ W1,
                                    const float* __restrict__ W2,
                                    const float* __restrict__ W3) {
    __shared__ float sW1[H * D];
    __shared__ float sw3col[D];
    int m = blockIdx.x;
    int k = threadIdx.x;
    for (int idx = k; idx < H * D; idx += H) sW1[idx] = W1[idx];
    if (k < D) sw3col[k] = W3[k * H + m];
    __syncthreads();
    float acc = 0.f;
#pragma unroll
    for (int j = 0; j < D; j++) acc += sW1[k * D + j] * sw3col[j];
    g_E[m * H + k] = W2[m * H + k] * acc;
}

__device__ __forceinline__ float ftanh(float z) {
    float e = __expf(2.f * z);
    return 1.f - __fdividef(2.f, e + 1.f);
}

__global__ __launch_bounds__(512, 1)
void ode_kernel(const float* __restrict__ x0,
                const float* __restrict__ W1g,
                const float* __restrict__ u1g,
                const float* __restrict__ b1g,
                const float* __restrict__ W2g,
                const float* __restrict__ b2g,
                const float* __restrict__ W3g,
                const float* __restrict__ b3g,
                const float* __restrict__ precg,
                float* __restrict__ out)
{
    __shared__ __align__(16) float sx[D];
    __shared__ __align__(16) float sh1[H];
    __shared__ __align__(16) float sd1[H];
    __shared__ __align__(16) float sh2[H];
    __shared__ float sp1[NSTEPS * 6 * D];
    __shared__ float sp2[NSTEPS * 6 * D];
    __shared__ float strc[NSTEPS * 6 * 8];
    __shared__ float sfin[16];

    const int tid  = threadIdx.x;
    const int lane = tid & 31;
    const int wid  = tid >> 5;
    const int b    = blockIdx.x;

    // roles
    const int  r1   = tid >> 2;         // layer-1 row (4 threads/row)
    const int  q1   = tid & 3;
    const bool low  = (tid < 256);      // layer-2: W2 rows  vs  E rows
    const int  rh   = (tid & 255) >> 1; // layer-2 row (2 threads/row)
    const int  half = tid & 1;
    const int  r3m  = (tid >> 3) & 31;  // layer-3 row (8 threads/row, low half)
    const int  sub  = tid & 7;

    // ---- register-resident weights ----
    float4 W1h[2], WE[16], W3c[4];
    {
        const float4* p = (const float4*)(W1g + r1 * D + q1 * 8);
        W1h[0] = p[0]; W1h[1] = p[1];
        const float* src = low ? W2g : g_E;
        const float4* q = (const float4*)(src + rh * H + half * 64);
#pragma unroll
        for (int i = 0; i < 16; i++) WE[i] = q[i];
        const float4* w3 = (const float4*)(W3g + r3m * H + sub * 16);
#pragma unroll
        for (int i = 0; i < 4; i++) W3c[i] = w3[i];
    }
    const float u1r = u1g[r1];
    const float b1r = b1g[r1];
    const float b2r = b2g[rh];
    const float b3r = b3g[r3m];
    const float prr = precg[r3m];

    // per-row ODE state in registers of the 32 "owner" threads (low, sub==0)
    float xreg = x0[b * D + r3m];   // current stage x for row r3m
    float yreg = xreg;              // integrated y for row r3m
    float kreg[6];

    if (tid < D) sx[tid] = x0[b * D + tid];
    __syncthreads();

#pragma unroll 1
    for (int step = 0; step < NSTEPS; step++) {
        const float t0 = (float)step * DTf;
#pragma unroll
        for (int s = 0; s < 6; s++) {
            const float t = t0 + Cc[s] * DTf;

            // ---- phase A: layer 1, 4 threads/row ----
            {
                const float4* xv = ((const float4*)sx) + q1 * 2;
                float4 x0v = xv[0], x1v = xv[1];
                float a0 = W1h[0].x * x0v.x + W1h[1].x * x1v.x;
                float a1 = W1h[0].y * x0v.y + W1h[1].y * x1v.y;
                float a2 = W1h[0].z * x0v.z + W1h[1].z * x1v.z;
                float a3 = W1h[0].w * x0v.w + W1h[1].w * x1v.w;
                float p = (a0 + a1) + (a2 + a3);
                p += __shfl_xor_sync(0xffffffffu, p, 1);
                p += __shfl_xor_sync(0xffffffffu, p, 2);
                if (q1 == 0) {
                    float h = ftanh(p + t * u1r + b1r);
                    sh1[r1] = h;
                    sd1[r1] = fmaf(-h, h, 1.f);
                }
            }
            __syncthreads();

            // ---- phase B: layer 2 rows (low: W2.h1 -> h2) | trace rows (high: E.d1) ----
            float pE;
            {
                const float4* vv = (low ? (const float4*)sh1
                                        : (const float4*)sd1) + half * 16;
                float a0 = 0.f, a1 = 0.f, a2 = 0.f, a3 = 0.f;
#pragma unroll
                for (int c = 0; c < 16; c++) {
                    float4 w = WE[c], v = vv[c];
                    a0 = fmaf(w.x, v.x, a0); a1 = fmaf(w.y, v.y, a1);
                    a2 = fmaf(w.z, v.z, a2); a3 = fmaf(w.w, v.w, a3);
                }
                float zsum = (a0 + a1) + (a2 + a3);
                if (low) {
                    zsum += __shfl_xor_sync(0xffffffffu, zsum, 1);
                    if (!half) sh2[rh] = ftanh(zsum + b2r);
                } else {
                    pE = zsum;   // keep half-row partial; combined in phase C reduce
                }
            }
            __syncthreads();

            // ---- phase C: layer 3 (low) | trace finalize (high) ----
            if (low) {
                const float4* hv = ((const float4*)sh2) + sub * 4;
                float a0 = 0.f, a1 = 0.f, a2 = 0.f, a3 = 0.f;
#pragma unroll
                for (int c = 0; c < 4; c++) {
                    float4 w = W3c[c], h4 = hv[c];
                    a0 = fmaf(w.x, h4.x, a0); a1 = fmaf(w.y, h4.y, a1);
                    a2 = fmaf(w.z, h4.z, a2); a3 = fmaf(w.w, h4.w, a3);
                }
                float o = (a0 + a1) + (a2 + a3);
                o += __shfl_xor_sync(0xffffffffu, o, 1);
                o += __shfl_xor_sync(0xffffffffu, o, 2);
                o += __shfl_xor_sync(0xffffffffu, o, 4);
                if (sub == 0) {
                    o += b3r;
                    kreg[s] = o;
                    float xs = xreg;
                    int idx = (step * 6 + s) * D + r3m;
                    sp1[idx] = (-0.5f * xs * xs - 0.5f * LOG2PI) * o;
                    sp2[idx] = (-prr * xs) * o;
                    float xn;
                    if (s < 5) {
                        float acc = Aa[s + 1][s] * o;
#pragma unroll
                        for (int l = 0; l < s; l++)
                            acc += Aa[s + 1][l] * kreg[l];
                        xn = yreg + DTf * acc;
                    } else {
                        float acc = Bb[0] * kreg[0] + Bb[2] * kreg[2]
                                  + Bb[3] * kreg[3] + Bb[4] * kreg[4]
                                  + Bb[5] * o;
                        xn = yreg + DTf * acc;
                        yreg = xn;
                    }
                    xreg = xn;
                    sx[r3m] = xn;
                }
            } else {
                float h2v = sh2[rh];
                float tr = fmaf(-h2v, h2v, 1.f) * pE;
#pragma unroll
                for (int o = 16; o; o >>= 1)
                    tr += __shfl_xor_sync(0xffffffffu, tr, o);
                if (lane == 0) strc[(step * 6 + s) * 8 + (wid - 8)] = tr;
            }
            __syncthreads();
        }
    }

    // ---- z output straight from owner registers ----
    if (low && sub == 0) out[b * D + r3m] = yreg;

    // ---- epilogue: warp w (0..7) reduces step w's 6 stages ----
    if (wid < 8) {
        float ldw = 0.f, klw = 0.f;
        const int stp = wid;
#pragma unroll
        for (int s = 0; s < 6; s++) {
            if (s == 1) continue;  // Bb[1] == 0
            int idx = stp * 6 + s;
            float v1 = sp1[idx * D + lane];
            float v2 = sp2[idx * D + lane];
            float v3 = (lane < 8) ? strc[idx * 8 + lane] : 0.f;
#pragma unroll
            for (int o = 16; o; o >>= 1) {
                v1 += __shfl_xor_sync(0xffffffffu, v1, o);
                v2 += __shfl_xor_sync(0xffffffffu, v2, o);
                v3 += __shfl_xor_sync(0xffffffffu, v3, o);
            }
            float t = (float)stp * DTf + Cc[s] * DTf;
            float omt = 1.f - t;
            float dlp = -v3;
            float dkl = -0.5f * omt * omt * v1
                        - 0.5f * omt * (1.f + t) * v2
                        + omt * dlp;
            ldw += Bb[s] * dlp;
            klw += Bb[s] * dkl;
        }
        if (lane == 0) { sfin[stp] = ldw; sfin[8 + stp] = klw; }
    }
    __syncthreads();

    if (wid == 0) {
        float a = (lane < 8) ? sfin[lane] : 0.f;
        float k = (lane < 8) ? sfin[8 + lane] : 0.f;
        float xv = x0[b * D + lane];
        float lp = -0.5f * xv * xv - 0.5f * LOG2PI;
#pragma unroll
        for (int o = 16; o; o >>= 1) {
            a  += __shfl_xor_sync(0xffffffffu, a, o);
            k  += __shfl_xor_sync(0xffffffffu, k, o);
            lp += __shfl_xor_sync(0xffffffffu, lp, o);
        }
        if (lane == 0) {
            out[NB * D + b]      = lp + DTf * a;
            out[NB * D + NB + b] = DTf * k;
        }
    }
}

extern "C" void kernel_launch(void* const* d_in, const int* in_sizes, int n_in,
                              void* d_out, int out_size) {
    const float* x0   = (const float*)d_in[0];
    const float* W1   = (const float*)d_in[1];
    const float* u1   = (const float*)d_in[2];
    const float* b1   = (const float*)d_in[3];
    const float* W2   = (const float*)d_in[4];
    const float* b2   = (const float*)d_in[5];
    const float* W3   = (const float*)d_in[6];
    const float* b3   = (const float*)d_in[7];
    const float* prec = (const float*)d_in[8];
    float* out = (float*)d_out;

    precompute_E_kernel<<<H, H>>>(W1, W2, W3);
    ode_kernel<<<NB, 512>>>(x0, W1, u1, b1, W2, b2, W3, b3, prec, out);
}

// round 5
// speedup vs baseline: 1.7593x; 1.7593x over previous
#include <cuda_runtime.h>
#include <math.h>

#define D 32
#define H 128
#define NB 128
#define NSTEPS 8
#define DTf 0.125f
#define LOG2PI 1.837877066409345483560659472811f

typedef unsigned long long u64;

// E[m*H+k] = W2[m,k] * (W1 @ W3)[k,m]   (input-independent)
__device__ float g_E[H * H];

static __device__ constexpr float Aa[6][5] = {
    {0.f, 0.f, 0.f, 0.f, 0.f},
    {0.2f, 0.f, 0.f, 0.f, 0.f},
    {3.f/40.f, 9.f/40.f, 0.f, 0.f, 0.f},
    {44.f/45.f, -56.f/15.f, 32.f/9.f, 0.f, 0.f},
    {19372.f/6561.f, -25360.f/2187.f, 64448.f/6561.f, -212.f/729.f, 0.f},
    {9017.f/3168.f, -355.f/33.f, 46732.f/5247.f, 49.f/176.f, -5103.f/18656.f}
};
static __device__ constexpr float Bb[6] = {
    35.f/384.f, 0.f, 500.f/1113.f, 125.f/192.f, -2187.f/6784.f, 11.f/84.f
};
static __device__ constexpr float Cc[6] = {0.f, 0.2f, 0.3f, 0.8f, 8.f/9.f, 1.f};

__global__ void precompute_E_kernel(const float* __restrict__ W1,
                                    const float* __restrict__ W2,
                                    const float* __restrict__ W3) {
    __shared__ float sW1[H * D];
    __shared__ float sw3col[D];
    int m = blockIdx.x;
    int k = threadIdx.x;
    for (int idx = k; idx < H * D; idx += H) sW1[idx] = W1[idx];
    if (k < D) sw3col[k] = W3[k * H + m];
    __syncthreads();
    float acc = 0.f;
#pragma unroll
    for (int j = 0; j < D; j++) acc += sW1[k * D + j] * sw3col[j];
    g_E[m * H + k] = W2[m * H + k] * acc;
}

__device__ __forceinline__ float ftanh(float z) {
    float e = __expf(2.f * z);
    return 1.f - __fdividef(2.f, e + 1.f);
}

// packed fp32x2 fma: acc.lo += a.lo*b.lo ; acc.hi += a.hi*b.hi
#define FFMA2(acc, a, b) \
    asm("fma.rn.f32x2 %0, %1, %2, %0;" : "+l"(acc) : "l"(a), "l"(b))

__device__ __forceinline__ float psum(u64 p) {
    float lo, hi;
    asm("mov.b64 {%0, %1}, %2;" : "=f"(lo), "=f"(hi) : "l"(p));
    return lo + hi;
}

__global__ __launch_bounds__(256, 1)
void ode_kernel(const float* __restrict__ x0,
                const float* __restrict__ W1g,
                const float* __restrict__ u1g,
                const float* __restrict__ b1g,
                const float* __restrict__ W2g,
                const float* __restrict__ b2g,
                const float* __restrict__ W3g,
                const float* __restrict__ b3g,
                const float* __restrict__ precg,
                float* __restrict__ out)
{
    __shared__ __align__(16) float sx[D];
    __shared__ __align__(16) float sh1[H];
    __shared__ __align__(16) float sd1[H];
    __shared__ __align__(16) float sh2[H];
    __shared__ float sp1[NSTEPS * 6 * D];
    __shared__ float sp2[NSTEPS * 6 * D];
    __shared__ float strc[NSTEPS * 6 * 8];
    __shared__ float sfin[16];

    const int tid  = threadIdx.x;
    const int lane = tid & 31;
    const int wid  = tid >> 5;
    const int r2   = tid >> 1;   // hidden row (pair)
    const int half = tid & 1;    // which K-half
    const int r3   = tid >> 3;   // output row (group of 8)
    const int sub  = tid & 7;
    const int b    = blockIdx.x;

    // ---- register-resident weights (as packed f32x2 pairs) ----
    ulonglong2 W1v[4], W2v[16], Ev[16], W3v[4];
    {
        const ulonglong2* p = (const ulonglong2*)(W1g + r2 * D + half * 16);
#pragma unroll
        for (int i = 0; i < 4; i++) W1v[i] = p[i];
        const ulonglong2* q = (const ulonglong2*)(W2g + r2 * H + half * 64);
        const ulonglong2* e = (const ulonglong2*)(g_E + r2 * H + half * 64);
#pragma unroll
        for (int i = 0; i < 16; i++) { W2v[i] = q[i]; Ev[i] = e[i]; }
        const ulonglong2* w3 = (const ulonglong2*)(W3g + r3 * H + sub * 16);
#pragma unroll
        for (int i = 0; i < 4; i++) W3v[i] = w3[i];
    }
    const float u1r = u1g[r2];
    const float b1r = b1g[r2];
    const float b2r = b2g[r2];
    const float b3r = b3g[r3];
    const float prr = precg[r3];

    // per-row ODE state in registers of the 32 "owner" threads (sub==0)
    float xreg = x0[b * D + r3];
    float yreg = xreg;
    float kreg[6];

    if (tid < D) sx[tid] = x0[b * D + tid];
    __syncthreads();

#pragma unroll 1
    for (int step = 0; step < NSTEPS; step++) {
        const float t0 = (float)step * DTf;
#pragma unroll
        for (int s = 0; s < 6; s++) {
            const float t = t0 + Cc[s] * DTf;

            // ---- phase A: layer 1, pair-split K, packed fma ----
            {
                const ulonglong2* xv = ((const ulonglong2*)sx) + half * 4;
                u64 a0 = 0ull, a1 = 0ull;
#pragma unroll
                for (int c = 0; c < 4; c++) {
                    ulonglong2 x2 = xv[c];
                    FFMA2(a0, W1v[c].x, x2.x);
                    FFMA2(a1, W1v[c].y, x2.y);
                }
                float p = psum(a0) + psum(a1);
                p += __shfl_xor_sync(0xffffffffu, p, 1);
                float h = ftanh(p + t * u1r + b1r);
                if (!half) {
                    sh1[r2] = h;
                    sd1[r2] = fmaf(-h, h, 1.f);
                }
            }
            __syncthreads();

            // ---- phase B: W2.h1 (h2) fused with E.d1 (trace), packed fma ----
            {
                const ulonglong2* hv = ((const ulonglong2*)sh1) + half * 16;
                const ulonglong2* dv = ((const ulonglong2*)sd1) + half * 16;
                u64 a0 = 0ull, a1 = 0ull, a2 = 0ull, a3 = 0ull;
                u64 g0 = 0ull, g1 = 0ull, g2 = 0ull, g3 = 0ull;
#pragma unroll
                for (int c = 0; c < 16; c += 2) {
                    ulonglong2 h0 = hv[c],   h1l = hv[c + 1];
                    ulonglong2 d0 = dv[c],   d1l = dv[c + 1];
                    ulonglong2 w0 = W2v[c],  w1l = W2v[c + 1];
                    ulonglong2 e0 = Ev[c],   e1l = Ev[c + 1];
                    FFMA2(a0, w0.x, h0.x);  FFMA2(a1, w0.y, h0.y);
                    FFMA2(a2, w1l.x, h1l.x); FFMA2(a3, w1l.y, h1l.y);
                    FFMA2(g0, e0.x, d0.x);  FFMA2(g1, e0.y, d0.y);
                    FFMA2(g2, e1l.x, d1l.x); FFMA2(g3, e1l.y, d1l.y);
                }
                float pz = (psum(a0) + psum(a1)) + (psum(a2) + psum(a3));
                pz += __shfl_xor_sync(0xffffffffu, pz, 1);
                float h2 = ftanh(pz + b2r);
                if (!half) sh2[r2] = h2;
                float tr = fmaf(-h2, h2, 1.f)
                         * ((psum(g0) + psum(g1)) + (psum(g2) + psum(g3)));
#pragma unroll
                for (int o = 16; o; o >>= 1)
                    tr += __shfl_xor_sync(0xffffffffu, tr, o);
                if (lane == 0) strc[(step * 6 + s) * 8 + wid] = tr;
            }
            __syncthreads();

            // ---- phase C: layer 3 (8 threads/row), packed fma + bookkeeping ----
            {
                const ulonglong2* hv = ((const ulonglong2*)sh2) + sub * 4;
                u64 a0 = 0ull, a1 = 0ull;
#pragma unroll
                for (int c = 0; c < 4; c++) {
                    ulonglong2 h4 = hv[c];
                    FFMA2(a0, W3v[c].x, h4.x);
                    FFMA2(a1, W3v[c].y, h4.y);
                }
                float o = psum(a0) + psum(a1);
                o += __shfl_xor_sync(0xffffffffu, o, 1);
                o += __shfl_xor_sync(0xffffffffu, o, 2);
                o += __shfl_xor_sync(0xffffffffu, o, 4);
                if (sub == 0) {
                    o += b3r;
                    kreg[s] = o;
                    float xs = xreg;
                    int idx = (step * 6 + s) * D + r3;
                    sp1[idx] = (-0.5f * xs * xs - 0.5f * LOG2PI) * o;
                    sp2[idx] = (-prr * xs) * o;
                    float xn;
                    if (s < 5) {
                        float acc = Aa[s + 1][s] * o;
#pragma unroll
                        for (int l = 0; l < s; l++)
                            acc += Aa[s + 1][l] * kreg[l];
                        xn = yreg + DTf * acc;
                    } else {
                        float acc = Bb[0] * kreg[0] + Bb[2] * kreg[2]
                                  + Bb[3] * kreg[3] + Bb[4] * kreg[4]
                                  + Bb[5] * o;
                        xn = yreg + DTf * acc;
                        yreg = xn;
                    }
                    xreg = xn;
                    sx[r3] = xn;
                }
            }
            __syncthreads();
        }
    }

    // ---- z output straight from owner registers ----
    if (sub == 0) out[b * D + r3] = yreg;

    // ---- epilogue: warp w (0..7) reduces step w's 6 stages ----
    {
        float ldw = 0.f, klw = 0.f;
        const int stp = wid;
#pragma unroll
        for (int s = 0; s < 6; s++) {
            if (s == 1) continue;  // Bb[1] == 0
            int idx = stp * 6 + s;
            float v1 = sp1[idx * D + lane];
            float v2 = sp2[idx * D + lane];
            float v3 = (lane < 8) ? strc[idx * 8 + lane] : 0.f;
#pragma unroll
            for (int o = 16; o; o >>= 1) {
                v1 += __shfl_xor_sync(0xffffffffu, v1, o);
                v2 += __shfl_xor_sync(0xffffffffu, v2, o);
                v3 += __shfl_xor_sync(0xffffffffu, v3, o);
            }
            float t = (float)stp * DTf + Cc[s] * DTf;
            float omt = 1.f - t;
            float dlp = -v3;
            float dkl = -0.5f * omt * omt * v1
                        - 0.5f * omt * (1.f + t) * v2
                        + omt * dlp;
            ldw += Bb[s] * dlp;
            klw += Bb[s] * dkl;
        }
        if (lane == 0) { sfin[stp] = ldw; sfin[8 + stp] = klw; }
    }
    __syncthreads();

    if (wid == 0) {
        float a = (lane < 8) ? sfin[lane] : 0.f;
        float k = (lane < 8) ? sfin[8 + lane] : 0.f;
        float xv = x0[b * D + lane];
        float lp = -0.5f * xv * xv - 0.5f * LOG2PI;
#pragma unroll
        for (int o = 16; o; o >>= 1) {
            a  += __shfl_xor_sync(0xffffffffu, a, o);
            k  += __shfl_xor_sync(0xffffffffu, k, o);
            lp += __shfl_xor_sync(0xffffffffu, lp, o);
        }
        if (lane == 0) {
            out[NB * D + b]      = lp + DTf * a;
            out[NB * D + NB + b] = DTf * k;
        }
    }
}

extern "C" void kernel_launch(void* const* d_in, const int* in_sizes, int n_in,
                              void* d_out, int out_size) {
    const float* x0   = (const float*)d_in[0];
    const float* W1   = (const float*)d_in[1];
    const float* u1   = (const float*)d_in[2];
    const float* b1   = (const float*)d_in[3];
    const float* W2   = (const float*)d_in[4];
    const float* b2   = (const float*)d_in[5];
    const float* W3   = (const float*)d_in[6];
    const float* b3   = (const float*)d_in[7];
    const float* prec = (const float*)d_in[8];
    float* out = (float*)d_out;

    precompute_E_kernel<<<H, H>>>(W1, W2, W3);
    ode_kernel<<<NB, 256>>>(x0, W1, u1, b1, W2, b2, W3, b3, prec, out);
}